// round 7
// baseline (speedup 1.0000x reference)
#include <cuda_runtime.h>

#define BATCH   262144
#define T_STEPS 20
#define BETAF   0.9f
#define THRESHF 1.0f
#define E 2

using u32 = unsigned int;
using u64 = unsigned long long;

__device__ __forceinline__ u64 pack2(float lo, float hi) {
    u64 r; asm("mov.b64 %0, {%1, %2};" : "=l"(r) : "f"(lo), "f"(hi)); return r;
}
__device__ __forceinline__ void unpack2(u64 v, float &lo, float &hi) {
    asm("mov.b64 {%0, %1}, %2;" : "=f"(lo), "=f"(hi) : "l"(v));
}
// Packed dual fp32 FMA (2 MACs / instruction on the fma pipe)
__device__ __forceinline__ u64 ffma2(u64 a, u64 b, u64 c) {
    u64 d; asm("fma.rn.f32x2 %0, %1, %2, %3;" : "=l"(d) : "l"(a), "l"(b), "l"(c)); return d;
}

#define ONE2 0x3F8000003F800000ull

// ---- static smem weights, half-major pair-packed (2 distinct warp addresses
// per LDS -> broadcast-cheap) ----
// w[(i*2+half)*P2 + p] = (W[2*(half*P2+p)][i], W[2*(half*P2+p)+1][i])
__shared__ u64 sW1[10 * 2 * 16];  // 10 -> 64, P2=16
__shared__ u64 sW2[64 * 2 * 8];   // 64 -> 32, P2=8
__shared__ u64 sW3[32 * 2 * 8];   // 32 -> 32, P2=8
__shared__ u64 sW4[32 * 2 * 4];   // 32 -> 16, P2=4
__shared__ u64 sW5[16 * 2 * 2];   // 16 -> 6 (padded to 8), P2=2

__device__ __forceinline__ void stage(u64* dst, const float* __restrict__ W,
                                      int NIN, int NOUT, int P2, int tid, int nthr) {
    int total = NIN * 2 * P2;
    for (int idx = tid; idx < total; idx += nthr) {
        int i = idx / (2 * P2);
        int r = idx % (2 * P2);
        int h = r / P2, p = r % P2;
        int j0 = 2 * (h * P2 + p);
        float a = (j0     < NOUT) ? W[j0 * NIN + i]       : 0.0f;
        float b = (j0 + 1 < NOUT) ? W[(j0 + 1) * NIN + i] : 0.0f;
        dst[(i * 2 + h) * P2 + p] = pack2(a, b);
    }
}

// LIF for one output pair; returns 2-bit spike mask. Same formula/order as rounds 1-6.
__device__ __forceinline__ u32 lif_pair(u64 acc, float &mA, float &mB) {
    float a0, a1; unpack2(acc, a0, a1);
    float r0 = mA > THRESHF ? THRESHF : 0.0f;
    float r1 = mB > THRESHF ? THRESHF : 0.0f;
    mA = fmaf(BETAF, mA, a0 - r0);
    mB = fmaf(BETAF, mB, a1 - r1);
    u32 m = 0;
    if (mA > THRESHF) m |= 1u;
    if (mB > THRESHF) m |= 2u;
    return m;
}

__global__ __launch_bounds__(128, 3) void lif_kernel(
    const float* __restrict__ x,
    const float* __restrict__ W1, const float* __restrict__ W2,
    const float* __restrict__ W3, const float* __restrict__ W4,
    const float* __restrict__ W5, float* __restrict__ out)
{
    int tid = threadIdx.x;
    stage(sW1, W1, 10, 64, 16, tid, 128);
    stage(sW2, W2, 64, 32,  8, tid, 128);
    stage(sW3, W3, 32, 32,  8, tid, 128);
    stage(sW4, W4, 32, 16,  4, tid, 128);
    stage(sW5, W5, 16,  6,  2, tid, 128);
    __syncthreads();

    const int half = tid & 1;                 // adjacent lanes = two halves of an element
    const size_t ebase = (size_t)blockIdx.x * 128 + (size_t)(tid >> 1) * E;

    // per-thread membrane state: half of every layer, for E elements
    float m1[E][32], m2[E][16], m3[E][16], m4[E][8], m5[E][4];
#pragma unroll
    for (int el = 0; el < E; ++el) {
#pragma unroll
        for (int k = 0; k < 32; ++k) m1[el][k] = 0.f;
#pragma unroll
        for (int k = 0; k < 16; ++k) { m2[el][k] = 0.f; m3[el][k] = 0.f; }
#pragma unroll
        for (int k = 0; k < 8; ++k)  m4[el][k] = 0.f;
#pragma unroll
        for (int k = 0; k < 4; ++k)  m5[el][k] = 0.f;
    }

#pragma unroll 1
    for (int t = 0; t < T_STEPS; ++t) {
        // ================= Layer 1: 10 -> 64 =================
        // per element sequential; two passes of 8 pairs (caps live accs at 8 u64)
        u32 l1lo[E], l1hi[E];
#pragma unroll
        for (int el = 0; el < E; ++el) {
            const float2* xp = (const float2*)(x + ((size_t)t * BATCH + ebase + el) * 10);
            float2 xv[5];
#pragma unroll
            for (int i = 0; i < 5; ++i) xv[i] = xp[i];

            u32 msk = 0;
#pragma unroll
            for (int pass = 0; pass < 2; ++pass) {
                u64 acc[8];
#pragma unroll
                for (int p = 0; p < 8; ++p) acc[p] = 0ull;
#pragma unroll
                for (int i = 0; i < 10; ++i) {
                    float xf = (i & 1) ? xv[i >> 1].y : xv[i >> 1].x;
                    u64 xd = pack2(xf, xf);
                    const ulonglong2* wp =
                        (const ulonglong2*)(sW1 + (i * 2 + half) * 16 + pass * 8);
#pragma unroll
                    for (int p2 = 0; p2 < 4; ++p2) {
                        ulonglong2 w = wp[p2];
                        acc[2 * p2]     = ffma2(xd, w.x, acc[2 * p2]);
                        acc[2 * p2 + 1] = ffma2(xd, w.y, acc[2 * p2 + 1]);
                    }
                }
#pragma unroll
                for (int p = 0; p < 8; ++p) {
                    int pg = pass * 8 + p;
                    msk |= lif_pair(acc[p], m1[el][2 * pg], m1[el][2 * pg + 1]) << (2 * pg);
                }
            }
            u32 oth = __shfl_xor_sync(0xffffffffu, msk, 1);
            l1lo[el] = half ? oth : msk;          // L1 outputs 0..31
            l1hi[el] = half ? msk : oth;          // L1 outputs 32..63
        }

        // ================= Layer 2: 64 -> 32 =================
        // two passes of 4 pairs; weights shared across both elements
        u32 f2[E];
        {
            u32 m16[E] = {0, 0};
#pragma unroll
            for (int pass = 0; pass < 2; ++pass) {
                u64 acc[E][4];
#pragma unroll
                for (int el = 0; el < E; ++el)
#pragma unroll
                    for (int p = 0; p < 4; ++p) acc[el][p] = 0ull;
#pragma unroll
                for (int blk = 0; blk < 2; ++blk) {
                    u32 mw0 = blk ? l1hi[0] : l1lo[0];
                    u32 mw1 = blk ? l1hi[1] : l1lo[1];
#pragma unroll
                    for (int ib = 0; ib < 32; ++ib) {
                        const ulonglong2* wp = (const ulonglong2*)
                            (sW2 + ((blk * 32 + ib) * 2 + half) * 8 + pass * 4);
                        ulonglong2 wa = wp[0], wb = wp[1];
                        u64 h0 = (mw0 & (1u << ib)) ? ONE2 : 0ull;
                        u64 h1 = (mw1 & (1u << ib)) ? ONE2 : 0ull;
                        acc[0][0] = ffma2(h0, wa.x, acc[0][0]);
                        acc[0][1] = ffma2(h0, wa.y, acc[0][1]);
                        acc[0][2] = ffma2(h0, wb.x, acc[0][2]);
                        acc[0][3] = ffma2(h0, wb.y, acc[0][3]);
                        acc[1][0] = ffma2(h1, wa.x, acc[1][0]);
                        acc[1][1] = ffma2(h1, wa.y, acc[1][1]);
                        acc[1][2] = ffma2(h1, wb.x, acc[1][2]);
                        acc[1][3] = ffma2(h1, wb.y, acc[1][3]);
                    }
                }
#pragma unroll
                for (int el = 0; el < E; ++el)
#pragma unroll
                    for (int p = 0; p < 4; ++p) {
                        int pg = pass * 4 + p;
                        m16[el] |= lif_pair(acc[el][p], m2[el][2 * pg], m2[el][2 * pg + 1])
                                   << (2 * pg);
                    }
            }
#pragma unroll
            for (int el = 0; el < E; ++el) {
                u32 oth = __shfl_xor_sync(0xffffffffu, m16[el], 1);
                f2[el] = half ? (oth | (m16[el] << 16)) : (m16[el] | (oth << 16));
            }
        }

        // ================= Layer 3: 32 -> 32 =================
        u32 f3[E];
        {
            u32 m16[E] = {0, 0};
#pragma unroll
            for (int pass = 0; pass < 2; ++pass) {
                u64 acc[E][4];
#pragma unroll
                for (int el = 0; el < E; ++el)
#pragma unroll
                    for (int p = 0; p < 4; ++p) acc[el][p] = 0ull;
#pragma unroll
                for (int i = 0; i < 32; ++i) {
                    const ulonglong2* wp = (const ulonglong2*)
                        (sW3 + (i * 2 + half) * 8 + pass * 4);
                    ulonglong2 wa = wp[0], wb = wp[1];
                    u64 h0 = (f2[0] & (1u << i)) ? ONE2 : 0ull;
                    u64 h1 = (f2[1] & (1u << i)) ? ONE2 : 0ull;
                    acc[0][0] = ffma2(h0, wa.x, acc[0][0]);
                    acc[0][1] = ffma2(h0, wa.y, acc[0][1]);
                    acc[0][2] = ffma2(h0, wb.x, acc[0][2]);
                    acc[0][3] = ffma2(h0, wb.y, acc[0][3]);
                    acc[1][0] = ffma2(h1, wa.x, acc[1][0]);
                    acc[1][1] = ffma2(h1, wa.y, acc[1][1]);
                    acc[1][2] = ffma2(h1, wb.x, acc[1][2]);
                    acc[1][3] = ffma2(h1, wb.y, acc[1][3]);
                }
#pragma unroll
                for (int el = 0; el < E; ++el)
#pragma unroll
                    for (int p = 0; p < 4; ++p) {
                        int pg = pass * 4 + p;
                        m16[el] |= lif_pair(acc[el][p], m3[el][2 * pg], m3[el][2 * pg + 1])
                                   << (2 * pg);
                    }
            }
#pragma unroll
            for (int el = 0; el < E; ++el) {
                u32 oth = __shfl_xor_sync(0xffffffffu, m16[el], 1);
                f3[el] = half ? (oth | (m16[el] << 16)) : (m16[el] | (oth << 16));
            }
        }

        // ================= Layer 4: 32 -> 16 (4 pairs per half, single pass) ======
        u32 f4[E];
        {
            u64 acc[E][4];
#pragma unroll
            for (int el = 0; el < E; ++el)
#pragma unroll
                for (int p = 0; p < 4; ++p) acc[el][p] = 0ull;
#pragma unroll
            for (int i = 0; i < 32; ++i) {
                const ulonglong2* wp = (const ulonglong2*)(sW4 + (i * 2 + half) * 4);
                ulonglong2 wa = wp[0], wb = wp[1];
                u64 h0 = (f3[0] & (1u << i)) ? ONE2 : 0ull;
                u64 h1 = (f3[1] & (1u << i)) ? ONE2 : 0ull;
                acc[0][0] = ffma2(h0, wa.x, acc[0][0]);
                acc[0][1] = ffma2(h0, wa.y, acc[0][1]);
                acc[0][2] = ffma2(h0, wb.x, acc[0][2]);
                acc[0][3] = ffma2(h0, wb.y, acc[0][3]);
                acc[1][0] = ffma2(h1, wa.x, acc[1][0]);
                acc[1][1] = ffma2(h1, wa.y, acc[1][1]);
                acc[1][2] = ffma2(h1, wb.x, acc[1][2]);
                acc[1][3] = ffma2(h1, wb.y, acc[1][3]);
            }
#pragma unroll
            for (int el = 0; el < E; ++el) {
                u32 m8 = 0;
#pragma unroll
                for (int p = 0; p < 4; ++p)
                    m8 |= lif_pair(acc[el][p], m4[el][2 * p], m4[el][2 * p + 1]) << (2 * p);
                u32 oth = __shfl_xor_sync(0xffffffffu, m8, 1);
                f4[el] = half ? (oth | (m8 << 8)) : (m8 | (oth << 8));
            }
        }

        // ================= Layer 5: 16 -> 6 (padded to 8; 2 pairs per half) =======
        {
            u64 acc[E][2];
#pragma unroll
            for (int el = 0; el < E; ++el) { acc[el][0] = 0ull; acc[el][1] = 0ull; }
#pragma unroll
            for (int i = 0; i < 16; ++i) {
                const ulonglong2* wp = (const ulonglong2*)(sW5 + (i * 2 + half) * 2);
                ulonglong2 wa = wp[0];
                u64 h0 = (f4[0] & (1u << i)) ? ONE2 : 0ull;
                u64 h1 = (f4[1] & (1u << i)) ? ONE2 : 0ull;
                acc[0][0] = ffma2(h0, wa.x, acc[0][0]);
                acc[0][1] = ffma2(h0, wa.y, acc[0][1]);
                acc[1][0] = ffma2(h1, wa.x, acc[1][0]);
                acc[1][1] = ffma2(h1, wa.y, acc[1][1]);
            }
#pragma unroll
            for (int el = 0; el < E; ++el) {
                float s[4];
#pragma unroll
                for (int p = 0; p < 2; ++p) {
                    float a0, a1; unpack2(acc[el][p], a0, a1);
                    float r0 = m5[el][2 * p]     > THRESHF ? THRESHF : 0.0f;
                    float r1 = m5[el][2 * p + 1] > THRESHF ? THRESHF : 0.0f;
                    float mm0 = fmaf(BETAF, m5[el][2 * p],     a0 - r0);
                    float mm1 = fmaf(BETAF, m5[el][2 * p + 1], a1 - r1);
                    m5[el][2 * p] = mm0; m5[el][2 * p + 1] = mm1;
                    s[2 * p]     = mm0 > THRESHF ? 1.0f : 0.0f;
                    s[2 * p + 1] = mm1 > THRESHF ? 1.0f : 0.0f;
                }
                float* op = out + ((size_t)t * BATCH + ebase + el) * 6;
                if (!half) {
                    *(float2*)(op)     = make_float2(s[0], s[1]);
                    *(float2*)(op + 2) = make_float2(s[2], s[3]);
                } else {
                    *(float2*)(op + 4) = make_float2(s[0], s[1]);
                }
            }
        }
    }
}

extern "C" void kernel_launch(void* const* d_in, const int* in_sizes, int n_in,
                              void* d_out, int out_size) {
    const float *x = nullptr, *W1 = nullptr, *W2 = nullptr, *W3 = nullptr,
                *W4 = nullptr, *W5 = nullptr;
    for (int i = 0; i < n_in; ++i) {
        const float* p = (const float*)d_in[i];
        switch (in_sizes[i]) {
            case 52428800: x  = p; break;  // (20, 262144, 10)
            case 640:      W1 = p; break;  // (64, 10)
            case 2048:     W2 = p; break;  // (32, 64)
            case 1024:     W3 = p; break;  // (32, 32)
            case 512:      W4 = p; break;  // (16, 32)
            case 96:       W5 = p; break;  // (6, 16)
            default: break;
        }
    }
    float* out = (float*)d_out;
    // 2 threads per element, E=2 elements per thread: 128 elements per 128-thread block
    lif_kernel<<<BATCH / 128, 128>>>(x, W1, W2, W3, W4, W5, out);
}

// round 8
// speedup vs baseline: 1.5012x; 1.5012x over previous
#include <cuda_runtime.h>

#define BATCH   262144
#define T_STEPS 20
#define BETAF   0.9f
#define THRESHF 1.0f

using u32 = unsigned int;
using u64 = unsigned long long;

__device__ __forceinline__ u64 pack2(float lo, float hi) {
    u64 r; asm("mov.b64 %0, {%1, %2};" : "=l"(r) : "f"(lo), "f"(hi)); return r;
}
__device__ __forceinline__ void unpack2(u64 v, float &lo, float &hi) {
    asm("mov.b64 {%0, %1}, %2;" : "=f"(lo), "=f"(hi) : "l"(v));
}
// Packed dual fp32 FMA (2 MACs / instruction on the fma pipe)
__device__ __forceinline__ u64 ffma2(u64 a, u64 b, u64 c) {
    u64 d; asm("fma.rn.f32x2 %0, %1, %2, %3;" : "=l"(d) : "l"(a), "l"(b), "l"(c)); return d;
}

#define ONE2 0x3F8000003F800000ull

// ---- static smem weights, quarter-major pair-packed with bank-spread padding ----
// w[(i*4 + q)*QS + p] = (W[2*(q*P4+p)][i], W[2*(q*P4+p)+1][i])
#define QS1 10  // P4=8
#define QS2 6   // P4=4
#define QS3 6   // P4=4
#define QS4 4   // P4=2
#define QS5 2   // P4=1
__shared__ u64 sW1[10 * 4 * QS1];
__shared__ u64 sW2[64 * 4 * QS2];
__shared__ u64 sW3[32 * 4 * QS3];
__shared__ u64 sW4[32 * 4 * QS4];
__shared__ u64 sW5[16 * 4 * QS5];

__device__ __forceinline__ void stage(u64* dst, const float* __restrict__ W,
                                      int NIN, int NOUT, int P4, int QS, int tid) {
    int total = NIN * 4 * P4;
    for (int idx = tid; idx < total; idx += 128) {
        int i = idx / (4 * P4);
        int r = idx % (4 * P4);
        int q = r / P4, p = r % P4;
        int j0 = 2 * (q * P4 + p);
        float a = (j0     < NOUT) ? W[j0 * NIN + i]       : 0.0f;
        float b = (j0 + 1 < NOUT) ? W[(j0 + 1) * NIN + i] : 0.0f;
        dst[(i * 4 + q) * QS + p] = pack2(a, b);
    }
}

// LIF for one output pair; returns 2-bit spike mask. Same formula/order as rounds 1-7.
__device__ __forceinline__ u32 lif_pair(u64 acc, float &mA, float &mB) {
    float a0, a1; unpack2(acc, a0, a1);
    float r0 = mA > THRESHF ? THRESHF : 0.0f;
    float r1 = mB > THRESHF ? THRESHF : 0.0f;
    mA = fmaf(BETAF, mA, a0 - r0);
    mB = fmaf(BETAF, mB, a1 - r1);
    u32 m = 0;
    if (mA > THRESHF) m |= 1u;
    if (mB > THRESHF) m |= 2u;
    return m;
}

// OR-reduce across the 4-lane quarter group (lane bits 0-1 = q).
__device__ __forceinline__ u32 bfly_or4(u32 v) {
    v |= __shfl_xor_sync(0xffffffffu, v, 1);
    v |= __shfl_xor_sync(0xffffffffu, v, 2);
    return v;
}

__global__ __launch_bounds__(128, 3) void lif_kernel(
    const float* __restrict__ x,
    const float* __restrict__ W1, const float* __restrict__ W2,
    const float* __restrict__ W3, const float* __restrict__ W4,
    const float* __restrict__ W5, float* __restrict__ out)
{
    int tid = threadIdx.x;
    stage(sW1, W1, 10, 64, 8, QS1, tid);
    stage(sW2, W2, 64, 32, 4, QS2, tid);
    stage(sW3, W3, 32, 32, 4, QS3, tid);
    stage(sW4, W4, 32, 16, 2, QS4, tid);
    stage(sW5, W5, 16,  6, 1, QS5, tid);
    __syncthreads();

    const int q = tid & 3;                         // quarter of each layer's outputs
    const size_t ebase = (size_t)blockIdx.x * 64 + (size_t)(tid >> 2) * 2;  // E=2

    const u64* w1q = sW1 + q * QS1;
    const u64* w2q = sW2 + q * QS2;
    const u64* w3q = sW3 + q * QS3;
    const u64* w4q = sW4 + q * QS4;
    const u64* w5q = sW5 + q * QS5;

    // membrane state: quarter of every layer, E=2 elements (38 floats each)
    float m1[2][16], m2[2][8], m3[2][8], m4[2][4], m5[2][2];
#pragma unroll
    for (int el = 0; el < 2; ++el) {
#pragma unroll
        for (int k = 0; k < 16; ++k) m1[el][k] = 0.f;
#pragma unroll
        for (int k = 0; k < 8; ++k) { m2[el][k] = 0.f; m3[el][k] = 0.f; }
#pragma unroll
        for (int k = 0; k < 4; ++k)  m4[el][k] = 0.f;
#pragma unroll
        for (int k = 0; k < 2; ++k)  m5[el][k] = 0.f;
    }

#pragma unroll 1
    for (int t = 0; t < T_STEPS; ++t) {
        // ---- Layer 1: 10 -> 64 (8 pairs per quarter), element-sequential ----
        u32 l1lo[2], l1hi[2];
#pragma unroll
        for (int el = 0; el < 2; ++el) {
            const float2* xp = (const float2*)(x + ((size_t)t * BATCH + ebase + el) * 10);
            float2 xv[5];
#pragma unroll
            for (int i = 0; i < 5; ++i) xv[i] = xp[i];

            u64 acc[8];
#pragma unroll
            for (int p = 0; p < 8; ++p) acc[p] = 0ull;
#pragma unroll
            for (int i = 0; i < 10; ++i) {
                const ulonglong2* wp = (const ulonglong2*)(w1q + i * (4 * QS1));
                ulonglong2 wa = wp[0], wb = wp[1], wc = wp[2], wd = wp[3];
                float xf = (i & 1) ? xv[i >> 1].y : xv[i >> 1].x;
                u64 xd = pack2(xf, xf);
                acc[0] = ffma2(xd, wa.x, acc[0]);
                acc[1] = ffma2(xd, wa.y, acc[1]);
                acc[2] = ffma2(xd, wb.x, acc[2]);
                acc[3] = ffma2(xd, wb.y, acc[3]);
                acc[4] = ffma2(xd, wc.x, acc[4]);
                acc[5] = ffma2(xd, wc.y, acc[5]);
                acc[6] = ffma2(xd, wd.x, acc[6]);
                acc[7] = ffma2(xd, wd.y, acc[7]);
            }
            u32 m16 = 0;
#pragma unroll
            for (int p = 0; p < 8; ++p)
                m16 |= lif_pair(acc[p], m1[el][2 * p], m1[el][2 * p + 1]) << (2 * p);
            u32 w0 = (q < 2)  ? (m16 << (q * 16)) : 0u;
            u32 w1 = (q >= 2) ? (m16 << ((q - 2) * 16)) : 0u;
            l1lo[el] = bfly_or4(w0);
            l1hi[el] = bfly_or4(w1);
        }

        // ---- Layer 2: 64 -> 32 (4 pairs per quarter), weights shared across E ----
        u64 acc2[2][4];
#pragma unroll
        for (int el = 0; el < 2; ++el)
#pragma unroll
            for (int p = 0; p < 4; ++p) acc2[el][p] = 0ull;
#pragma unroll
        for (int i = 0; i < 64; ++i) {
            const ulonglong2* wp = (const ulonglong2*)(w2q + i * (4 * QS2));
            ulonglong2 wa = wp[0], wb = wp[1];
            u32 bit = 1u << (i & 31);
            u64 h0 = (((i < 32) ? l1lo[0] : l1hi[0]) & bit) ? ONE2 : 0ull;
            u64 h1 = (((i < 32) ? l1lo[1] : l1hi[1]) & bit) ? ONE2 : 0ull;
            acc2[0][0] = ffma2(h0, wa.x, acc2[0][0]);
            acc2[0][1] = ffma2(h0, wa.y, acc2[0][1]);
            acc2[0][2] = ffma2(h0, wb.x, acc2[0][2]);
            acc2[0][3] = ffma2(h0, wb.y, acc2[0][3]);
            acc2[1][0] = ffma2(h1, wa.x, acc2[1][0]);
            acc2[1][1] = ffma2(h1, wa.y, acc2[1][1]);
            acc2[1][2] = ffma2(h1, wb.x, acc2[1][2]);
            acc2[1][3] = ffma2(h1, wb.y, acc2[1][3]);
        }
        u32 f2[2];
#pragma unroll
        for (int el = 0; el < 2; ++el) {
            u32 m8 = 0;
#pragma unroll
            for (int p = 0; p < 4; ++p)
                m8 |= lif_pair(acc2[el][p], m2[el][2 * p], m2[el][2 * p + 1]) << (2 * p);
            f2[el] = bfly_or4(m8 << (q * 8));
        }

        // ---- Layer 3: 32 -> 32 ----
        u64 acc3[2][4];
#pragma unroll
        for (int el = 0; el < 2; ++el)
#pragma unroll
            for (int p = 0; p < 4; ++p) acc3[el][p] = 0ull;
#pragma unroll
        for (int i = 0; i < 32; ++i) {
            const ulonglong2* wp = (const ulonglong2*)(w3q + i * (4 * QS3));
            ulonglong2 wa = wp[0], wb = wp[1];
            u32 bit = 1u << i;
            u64 h0 = (f2[0] & bit) ? ONE2 : 0ull;
            u64 h1 = (f2[1] & bit) ? ONE2 : 0ull;
            acc3[0][0] = ffma2(h0, wa.x, acc3[0][0]);
            acc3[0][1] = ffma2(h0, wa.y, acc3[0][1]);
            acc3[0][2] = ffma2(h0, wb.x, acc3[0][2]);
            acc3[0][3] = ffma2(h0, wb.y, acc3[0][3]);
            acc3[1][0] = ffma2(h1, wa.x, acc3[1][0]);
            acc3[1][1] = ffma2(h1, wa.y, acc3[1][1]);
            acc3[1][2] = ffma2(h1, wb.x, acc3[1][2]);
            acc3[1][3] = ffma2(h1, wb.y, acc3[1][3]);
        }
        u32 f3[2];
#pragma unroll
        for (int el = 0; el < 2; ++el) {
            u32 m8 = 0;
#pragma unroll
            for (int p = 0; p < 4; ++p)
                m8 |= lif_pair(acc3[el][p], m3[el][2 * p], m3[el][2 * p + 1]) << (2 * p);
            f3[el] = bfly_or4(m8 << (q * 8));
        }

        // ---- Layer 4: 32 -> 16 (2 pairs per quarter) ----
        u64 acc4[2][2];
#pragma unroll
        for (int el = 0; el < 2; ++el) { acc4[el][0] = 0ull; acc4[el][1] = 0ull; }
#pragma unroll
        for (int i = 0; i < 32; ++i) {
            const ulonglong2* wp = (const ulonglong2*)(w4q + i * (4 * QS4));
            ulonglong2 wa = wp[0];
            u32 bit = 1u << i;
            u64 h0 = (f3[0] & bit) ? ONE2 : 0ull;
            u64 h1 = (f3[1] & bit) ? ONE2 : 0ull;
            acc4[0][0] = ffma2(h0, wa.x, acc4[0][0]);
            acc4[0][1] = ffma2(h0, wa.y, acc4[0][1]);
            acc4[1][0] = ffma2(h1, wa.x, acc4[1][0]);
            acc4[1][1] = ffma2(h1, wa.y, acc4[1][1]);
        }
        u32 f4[2];
#pragma unroll
        for (int el = 0; el < 2; ++el) {
            u32 m4b = lif_pair(acc4[el][0], m4[el][0], m4[el][1])
                    | (lif_pair(acc4[el][1], m4[el][2], m4[el][3]) << 2);
            f4[el] = bfly_or4(m4b << (q * 4));
        }

        // ---- Layer 5: 16 -> 6 (padded to 8; 1 pair per quarter) ----
        u64 acc5[2];
        acc5[0] = 0ull; acc5[1] = 0ull;
#pragma unroll
        for (int i = 0; i < 16; ++i) {
            u64 w = w5q[i * (4 * QS5)];
            u32 bit = 1u << i;
            u64 h0 = (f4[0] & bit) ? ONE2 : 0ull;
            u64 h1 = (f4[1] & bit) ? ONE2 : 0ull;
            acc5[0] = ffma2(h0, w, acc5[0]);
            acc5[1] = ffma2(h1, w, acc5[1]);
        }
#pragma unroll
        for (int el = 0; el < 2; ++el) {
            float a0, a1; unpack2(acc5[el], a0, a1);
            float r0 = m5[el][0] > THRESHF ? THRESHF : 0.0f;
            float r1 = m5[el][1] > THRESHF ? THRESHF : 0.0f;
            float mm0 = fmaf(BETAF, m5[el][0], a0 - r0);
            float mm1 = fmaf(BETAF, m5[el][1], a1 - r1);
            m5[el][0] = mm0; m5[el][1] = mm1;
            if (q < 3) {
                float2 o;
                o.x = mm0 > THRESHF ? 1.0f : 0.0f;
                o.y = mm1 > THRESHF ? 1.0f : 0.0f;
                *(float2*)(out + ((size_t)t * BATCH + ebase + el) * 6 + q * 2) = o;
            }
        }
    }
}

extern "C" void kernel_launch(void* const* d_in, const int* in_sizes, int n_in,
                              void* d_out, int out_size) {
    const float *x = nullptr, *W1 = nullptr, *W2 = nullptr, *W3 = nullptr,
                *W4 = nullptr, *W5 = nullptr;
    for (int i = 0; i < n_in; ++i) {
        const float* p = (const float*)d_in[i];
        switch (in_sizes[i]) {
            case 52428800: x  = p; break;  // (20, 262144, 10)
            case 640:      W1 = p; break;  // (64, 10)
            case 2048:     W2 = p; break;  // (32, 64)
            case 1024:     W3 = p; break;  // (32, 32)
            case 512:      W4 = p; break;  // (16, 32)
            case 96:       W5 = p; break;  // (6, 16)
            default: break;
        }
    }
    float* out = (float*)d_out;
    // 4 threads per element, E=2 elements per thread: 64 elements per 128-thread block
    lif_kernel<<<BATCH / 64, 128>>>(x, W1, W2, W3, W4, W5, out);
}

// round 9
// speedup vs baseline: 2.1359x; 1.4228x over previous
#include <cuda_runtime.h>

#define BATCH   262144
#define T_STEPS 20
#define BETAF   0.9f
#define THRESHF 1.0f

using u32 = unsigned int;
using u64 = unsigned long long;

__device__ __forceinline__ u64 pack2(float lo, float hi) {
    u64 r; asm("mov.b64 %0, {%1, %2};" : "=l"(r) : "f"(lo), "f"(hi)); return r;
}
__device__ __forceinline__ void unpack2(u64 v, float &lo, float &hi) {
    asm("mov.b64 {%0, %1}, %2;" : "=f"(lo), "=f"(hi) : "l"(v));
}
// Packed dual fp32 FMA (2 MACs / instruction on the fma pipe)
__device__ __forceinline__ u64 ffma2(u64 a, u64 b, u64 c) {
    u64 d; asm("fma.rn.f32x2 %0, %1, %2, %3;" : "=l"(d) : "l"(a), "l"(b), "l"(c)); return d;
}

#define ONE2 0x3F8000003F800000ull

// ---- static smem weights, quarter-contiguous (warp-uniform addressing) ----
// layout [q][i][p]: w[(q*NIN + i)*P4 + p] = (W[2*P4*q + 2p][i], W[...+1][i])
__shared__ u64 sW1[4 * 10 * 8];  // 10 -> 64, P4=8
__shared__ u64 sW2[4 * 64 * 4];  // 64 -> 32, P4=4
__shared__ u64 sW3[4 * 32 * 4];  // 32 -> 32, P4=4
__shared__ u64 sW4[4 * 32 * 2];  // 32 -> 16, P4=2
__shared__ u64 sW5[4 * 16 * 1];  // 16 -> 6 (padded to 8), P4=1
// spike-mask exchange buffer: [layer regions][64 elems][4 quarters] (u32)
__shared__ u32 spk[4 * 64 * 4];

__device__ __forceinline__ void stage(u64* dst, const float* __restrict__ W,
                                      int NIN, int NOUT, int P4, int tid) {
    int total = 4 * NIN * P4;
    for (int idx = tid; idx < total; idx += 128) {
        int q = idx / (NIN * P4);
        int r = idx % (NIN * P4);
        int i = r / P4, p = r % P4;
        int j0 = q * (2 * P4) + 2 * p;
        float a = (j0     < NOUT) ? W[j0 * NIN + i]       : 0.0f;
        float b = (j0 + 1 < NOUT) ? W[(j0 + 1) * NIN + i] : 0.0f;
        dst[idx] = pack2(a, b);
    }
}

// LIF for one output pair; returns 2-bit spike mask. Same formula/order as rounds 1-8.
__device__ __forceinline__ u32 lif_pair(u64 acc, float &mA, float &mB) {
    float a0, a1; unpack2(acc, a0, a1);
    float r0 = mA > THRESHF ? THRESHF : 0.0f;
    float r1 = mB > THRESHF ? THRESHF : 0.0f;
    mA = fmaf(BETAF, mA, a0 - r0);
    mB = fmaf(BETAF, mB, a1 - r1);
    u32 m = 0;
    if (mA > THRESHF) m |= 1u;
    if (mB > THRESHF) m |= 2u;
    return m;
}

__global__ __launch_bounds__(128, 3) void lif_kernel(
    const float* __restrict__ x,
    const float* __restrict__ W1, const float* __restrict__ W2,
    const float* __restrict__ W3, const float* __restrict__ W4,
    const float* __restrict__ W5, float* __restrict__ out)
{
    const int tid = threadIdx.x;
    stage(sW1, W1, 10, 64, 8, tid);
    stage(sW2, W2, 64, 32, 4, tid);
    stage(sW3, W3, 32, 32, 4, tid);
    stage(sW4, W4, 32, 16, 2, tid);
    stage(sW5, W5, 16,  6, 1, tid);
    __syncthreads();

    const int wq   = tid >> 5;      // warp = quarter of every layer's outputs
    const int lane = tid & 31;
    const int eloc0 = lane * 2;     // two local elements per thread
    const size_t eglob = (size_t)blockIdx.x * 64 + eloc0;

    const u64* w1 = sW1 + wq * (10 * 8);
    const u64* w2 = sW2 + wq * (64 * 4);
    const u64* w3 = sW3 + wq * (32 * 4);
    const u64* w4 = sW4 + wq * (32 * 2);
    const u64* w5 = sW5 + wq * 16;
    u32* sp1 = spk;          // [64][4]
    u32* sp2 = spk + 256;
    u32* sp3 = spk + 512;
    u32* sp4 = spk + 768;

    // membrane state: quarter of every layer, E=2 elements (38 floats each)
    float m1[2][16], m2[2][8], m3[2][8], m4[2][4], m5[2][2];
#pragma unroll
    for (int el = 0; el < 2; ++el) {
#pragma unroll
        for (int k = 0; k < 16; ++k) m1[el][k] = 0.f;
#pragma unroll
        for (int k = 0; k < 8; ++k) { m2[el][k] = 0.f; m3[el][k] = 0.f; }
#pragma unroll
        for (int k = 0; k < 4; ++k)  m4[el][k] = 0.f;
#pragma unroll
        for (int k = 0; k < 2; ++k)  m5[el][k] = 0.f;
    }

#pragma unroll 1
    for (int t = 0; t < T_STEPS; ++t) {
        // ================= Layer 1: 10 -> 64 (8 pairs per warp) =================
#pragma unroll
        for (int el = 0; el < 2; ++el) {
            const float2* xp = (const float2*)(x + ((size_t)t * BATCH + eglob + el) * 10);
            float2 xv[5];
#pragma unroll
            for (int i = 0; i < 5; ++i) xv[i] = xp[i];

            u64 acc[8];
#pragma unroll
            for (int p = 0; p < 8; ++p) acc[p] = 0ull;
#pragma unroll
            for (int i = 0; i < 10; ++i) {
                const ulonglong2* wp = (const ulonglong2*)(w1 + i * 8);
                ulonglong2 wa = wp[0], wb = wp[1], wc = wp[2], wd = wp[3];
                float xf = (i & 1) ? xv[i >> 1].y : xv[i >> 1].x;
                u64 xd = pack2(xf, xf);
                acc[0] = ffma2(xd, wa.x, acc[0]);
                acc[1] = ffma2(xd, wa.y, acc[1]);
                acc[2] = ffma2(xd, wb.x, acc[2]);
                acc[3] = ffma2(xd, wb.y, acc[3]);
                acc[4] = ffma2(xd, wc.x, acc[4]);
                acc[5] = ffma2(xd, wc.y, acc[5]);
                acc[6] = ffma2(xd, wd.x, acc[6]);
                acc[7] = ffma2(xd, wd.y, acc[7]);
            }
            u32 m16 = 0;
#pragma unroll
            for (int p = 0; p < 8; ++p)
                m16 |= lif_pair(acc[p], m1[el][2 * p], m1[el][2 * p + 1]) << (2 * p);
            // pre-shift into its 16-bit slot of the lo/hi word
            sp1[(eloc0 + el) * 4 + wq] = (wq & 1) ? (m16 << 16) : m16;
        }
        __syncthreads();
        u32 lo[2], hi[2];
#pragma unroll
        for (int el = 0; el < 2; ++el) {
            uint4 r = *(const uint4*)&sp1[(eloc0 + el) * 4];
            lo[el] = r.x | r.y;     // L1 outputs 0..31
            hi[el] = r.z | r.w;     // L1 outputs 32..63
        }

        // ================= Layer 2: 64 -> 32 (4 pairs per warp) =================
        u64 acc2[2][4];
#pragma unroll
        for (int el = 0; el < 2; ++el)
#pragma unroll
            for (int p = 0; p < 4; ++p) acc2[el][p] = 0ull;
#pragma unroll
        for (int i = 0; i < 64; ++i) {
            const ulonglong2* wp = (const ulonglong2*)(w2 + i * 4);
            ulonglong2 wa = wp[0], wb = wp[1];
            u32 bit = 1u << (i & 31);
            u64 h0 = (((i < 32) ? lo[0] : hi[0]) & bit) ? ONE2 : 0ull;
            u64 h1 = (((i < 32) ? lo[1] : hi[1]) & bit) ? ONE2 : 0ull;
            acc2[0][0] = ffma2(h0, wa.x, acc2[0][0]);
            acc2[0][1] = ffma2(h0, wa.y, acc2[0][1]);
            acc2[0][2] = ffma2(h0, wb.x, acc2[0][2]);
            acc2[0][3] = ffma2(h0, wb.y, acc2[0][3]);
            acc2[1][0] = ffma2(h1, wa.x, acc2[1][0]);
            acc2[1][1] = ffma2(h1, wa.y, acc2[1][1]);
            acc2[1][2] = ffma2(h1, wb.x, acc2[1][2]);
            acc2[1][3] = ffma2(h1, wb.y, acc2[1][3]);
        }
#pragma unroll
        for (int el = 0; el < 2; ++el) {
            u32 m8 = 0;
#pragma unroll
            for (int p = 0; p < 4; ++p)
                m8 |= lif_pair(acc2[el][p], m2[el][2 * p], m2[el][2 * p + 1]) << (2 * p);
            sp2[(eloc0 + el) * 4 + wq] = m8 << (wq * 8);
        }
        __syncthreads();
        u32 f2[2];
#pragma unroll
        for (int el = 0; el < 2; ++el) {
            uint4 r = *(const uint4*)&sp2[(eloc0 + el) * 4];
            f2[el] = (r.x | r.y) | (r.z | r.w);
        }

        // ================= Layer 3: 32 -> 32 =================
        u64 acc3[2][4];
#pragma unroll
        for (int el = 0; el < 2; ++el)
#pragma unroll
            for (int p = 0; p < 4; ++p) acc3[el][p] = 0ull;
#pragma unroll
        for (int i = 0; i < 32; ++i) {
            const ulonglong2* wp = (const ulonglong2*)(w3 + i * 4);
            ulonglong2 wa = wp[0], wb = wp[1];
            u32 bit = 1u << i;
            u64 h0 = (f2[0] & bit) ? ONE2 : 0ull;
            u64 h1 = (f2[1] & bit) ? ONE2 : 0ull;
            acc3[0][0] = ffma2(h0, wa.x, acc3[0][0]);
            acc3[0][1] = ffma2(h0, wa.y, acc3[0][1]);
            acc3[0][2] = ffma2(h0, wb.x, acc3[0][2]);
            acc3[0][3] = ffma2(h0, wb.y, acc3[0][3]);
            acc3[1][0] = ffma2(h1, wa.x, acc3[1][0]);
            acc3[1][1] = ffma2(h1, wa.y, acc3[1][1]);
            acc3[1][2] = ffma2(h1, wb.x, acc3[1][2]);
            acc3[1][3] = ffma2(h1, wb.y, acc3[1][3]);
        }
#pragma unroll
        for (int el = 0; el < 2; ++el) {
            u32 m8 = 0;
#pragma unroll
            for (int p = 0; p < 4; ++p)
                m8 |= lif_pair(acc3[el][p], m3[el][2 * p], m3[el][2 * p + 1]) << (2 * p);
            sp3[(eloc0 + el) * 4 + wq] = m8 << (wq * 8);
        }
        __syncthreads();
        u32 f3[2];
#pragma unroll
        for (int el = 0; el < 2; ++el) {
            uint4 r = *(const uint4*)&sp3[(eloc0 + el) * 4];
            f3[el] = (r.x | r.y) | (r.z | r.w);
        }

        // ================= Layer 4: 32 -> 16 (2 pairs per warp) =================
        u64 acc4[2][2];
#pragma unroll
        for (int el = 0; el < 2; ++el) { acc4[el][0] = 0ull; acc4[el][1] = 0ull; }
#pragma unroll
        for (int i = 0; i < 32; ++i) {
            const ulonglong2* wp = (const ulonglong2*)(w4 + i * 2);
            ulonglong2 wa = wp[0];
            u32 bit = 1u << i;
            u64 h0 = (f3[0] & bit) ? ONE2 : 0ull;
            u64 h1 = (f3[1] & bit) ? ONE2 : 0ull;
            acc4[0][0] = ffma2(h0, wa.x, acc4[0][0]);
            acc4[0][1] = ffma2(h0, wa.y, acc4[0][1]);
            acc4[1][0] = ffma2(h1, wa.x, acc4[1][0]);
            acc4[1][1] = ffma2(h1, wa.y, acc4[1][1]);
        }
#pragma unroll
        for (int el = 0; el < 2; ++el) {
            u32 m4b = lif_pair(acc4[el][0], m4[el][0], m4[el][1])
                    | (lif_pair(acc4[el][1], m4[el][2], m4[el][3]) << 2);
            sp4[(eloc0 + el) * 4 + wq] = m4b << (wq * 4);
        }
        __syncthreads();
        u32 f4[2];
#pragma unroll
        for (int el = 0; el < 2; ++el) {
            uint4 r = *(const uint4*)&sp4[(eloc0 + el) * 4];
            f4[el] = (r.x | r.y) | (r.z | r.w);
        }

        // ================= Layer 5: 16 -> 6 (padded; 1 pair per warp) ============
        u64 acc5[2];
        acc5[0] = 0ull; acc5[1] = 0ull;
#pragma unroll
        for (int i = 0; i < 16; ++i) {
            u64 w = w5[i];
            u32 bit = 1u << i;
            u64 h0 = (f4[0] & bit) ? ONE2 : 0ull;
            u64 h1 = (f4[1] & bit) ? ONE2 : 0ull;
            acc5[0] = ffma2(h0, w, acc5[0]);
            acc5[1] = ffma2(h1, w, acc5[1]);
        }
#pragma unroll
        for (int el = 0; el < 2; ++el) {
            float a0, a1; unpack2(acc5[el], a0, a1);
            float r0 = m5[el][0] > THRESHF ? THRESHF : 0.0f;
            float r1 = m5[el][1] > THRESHF ? THRESHF : 0.0f;
            float mm0 = fmaf(BETAF, m5[el][0], a0 - r0);
            float mm1 = fmaf(BETAF, m5[el][1], a1 - r1);
            m5[el][0] = mm0; m5[el][1] = mm1;
            if (wq < 3) {
                float2 o;
                o.x = mm0 > THRESHF ? 1.0f : 0.0f;
                o.y = mm1 > THRESHF ? 1.0f : 0.0f;
                *(float2*)(out + ((size_t)t * BATCH + eglob + el) * 6 + wq * 2) = o;
            }
        }
    }
}

extern "C" void kernel_launch(void* const* d_in, const int* in_sizes, int n_in,
                              void* d_out, int out_size) {
    const float *x = nullptr, *W1 = nullptr, *W2 = nullptr, *W3 = nullptr,
                *W4 = nullptr, *W5 = nullptr;
    for (int i = 0; i < n_in; ++i) {
        const float* p = (const float*)d_in[i];
        switch (in_sizes[i]) {
            case 52428800: x  = p; break;  // (20, 262144, 10)
            case 640:      W1 = p; break;  // (64, 10)
            case 2048:     W2 = p; break;  // (32, 64)
            case 1024:     W3 = p; break;  // (32, 32)
            case 512:      W4 = p; break;  // (16, 32)
            case 96:       W5 = p; break;  // (6, 16)
            default: break;
        }
    }
    float* out = (float*)d_out;
    // 4 warps per block = 4 output-quarters; 32 lanes x E=2 -> 64 elements per block
    lif_kernel<<<BATCH / 64, 128>>>(x, W1, W2, W3, W4, W5, out);
}

// round 11
// speedup vs baseline: 2.2572x; 1.0568x over previous
#include <cuda_runtime.h>

#define BATCH   262144
#define T_STEPS 20
#define BETAF   0.9f
#define THRESHF 1.0f

using u32 = unsigned int;
using u64 = unsigned long long;

__device__ __forceinline__ u64 pack2(float lo, float hi) {
    u64 r; asm("mov.b64 %0, {%1, %2};" : "=l"(r) : "f"(lo), "f"(hi)); return r;
}
__device__ __forceinline__ void unpack2(u64 v, float &lo, float &hi) {
    asm("mov.b64 {%0, %1}, %2;" : "=f"(lo), "=f"(hi) : "l"(v));
}
// Packed dual fp32 FMA (2 MACs / instruction on the fma pipe)
__device__ __forceinline__ u64 ffma2(u64 a, u64 b, u64 c) {
    u64 d; asm("fma.rn.f32x2 %0, %1, %2, %3;" : "=l"(d) : "l"(a), "l"(b), "l"(c)); return d;
}

#define ONE2 0x3F8000003F800000ull

// ---- static smem weights, quarter-contiguous (warp-uniform addressing) ----
// layout [q][i][p]: w[(q*NIN + i)*P4 + p] = (W[2*P4*q + 2p][i], W[...+1][i])
__shared__ u64 sW1[4 * 10 * 8];  // 10 -> 64, P4=8
__shared__ u64 sW2[4 * 64 * 4];  // 64 -> 32, P4=4
__shared__ u64 sW3[4 * 32 * 4];  // 32 -> 32, P4=4
__shared__ u64 sW4[4 * 32 * 2];  // 32 -> 16, P4=2
__shared__ u64 sW5[4 * 16 * 1];  // 16 -> 6 (padded to 8), P4=1
// spike-mask exchange: [region][wq][el][lane] -> every STS/LDS is lane-consecutive
__shared__ u32 spk[4 * 4 * 2 * 32];

__device__ __forceinline__ void stage(u64* dst, const float* __restrict__ W,
                                      int NIN, int NOUT, int P4, int tid) {
    int total = 4 * NIN * P4;
    for (int idx = tid; idx < total; idx += 128) {
        int q = idx / (NIN * P4);
        int r = idx % (NIN * P4);
        int i = r / P4, p = r % P4;
        int j0 = q * (2 * P4) + 2 * p;
        float a = (j0     < NOUT) ? W[j0 * NIN + i]       : 0.0f;
        float b = (j0 + 1 < NOUT) ? W[(j0 + 1) * NIN + i] : 0.0f;
        dst[idx] = pack2(a, b);
    }
}

// LIF for one output pair; returns 2-bit spike mask. Same formula/order as rounds 1-10.
__device__ __forceinline__ u32 lif_pair(u64 acc, float &mA, float &mB) {
    float a0, a1; unpack2(acc, a0, a1);
    float r0 = mA > THRESHF ? THRESHF : 0.0f;
    float r1 = mB > THRESHF ? THRESHF : 0.0f;
    mA = fmaf(BETAF, mA, a0 - r0);
    mB = fmaf(BETAF, mB, a1 - r1);
    u32 m = 0;
    if (mA > THRESHF) m |= 1u;
    if (mB > THRESHF) m |= 2u;
    return m;
}

__global__ __launch_bounds__(128, 3) void lif_kernel(
    const float* __restrict__ x,
    const float* __restrict__ W1, const float* __restrict__ W2,
    const float* __restrict__ W3, const float* __restrict__ W4,
    const float* __restrict__ W5, float* __restrict__ out)
{
    const int tid = threadIdx.x;
    stage(sW1, W1, 10, 64, 8, tid);
    stage(sW2, W2, 64, 32, 4, tid);
    stage(sW3, W3, 32, 32, 4, tid);
    stage(sW4, W4, 32, 16, 2, tid);
    stage(sW5, W5, 16,  6, 1, tid);
    __syncthreads();

    const int wq   = tid >> 5;      // warp = quarter of every layer's outputs
    const int lane = tid & 31;
    const size_t eglob = (size_t)blockIdx.x * 64 + lane * 2;  // elements 2*lane, 2*lane+1

    const u64* w1 = sW1 + wq * (10 * 8);
    const u64* w2 = sW2 + wq * (64 * 4);
    const u64* w3 = sW3 + wq * (32 * 4);
    const u64* w4 = sW4 + wq * (32 * 2);
    const u64* w5 = sW5 + wq * 16;
    // per-region exchange bases
    u32* sp1 = spk;           // [4wq][2el][32lane]
    u32* sp2 = spk + 256;
    u32* sp3 = spk + 512;
    u32* sp4 = spk + 768;
    // producer slots (lane-consecutive within a warp)
    u32* my1 = sp1 + wq * 64 + lane;
    u32* my2 = sp2 + wq * 64 + lane;
    u32* my3 = sp3 + wq * 64 + lane;
    u32* my4 = sp4 + wq * 64 + lane;

    // membrane state: quarter of every layer, E=2 elements (38 floats each)
    float m1[2][16], m2[2][8], m3[2][8], m4[2][4], m5[2][2];
#pragma unroll
    for (int el = 0; el < 2; ++el) {
#pragma unroll
        for (int k = 0; k < 16; ++k) m1[el][k] = 0.f;
#pragma unroll
        for (int k = 0; k < 8; ++k) { m2[el][k] = 0.f; m3[el][k] = 0.f; }
#pragma unroll
        for (int k = 0; k < 4; ++k)  m4[el][k] = 0.f;
#pragma unroll
        for (int k = 0; k < 2; ++k)  m5[el][k] = 0.f;
    }

#pragma unroll 1
    for (int t = 0; t < T_STEPS; ++t) {
        // ================= Layer 1: 10 -> 64 (8 pairs per warp) =================
#pragma unroll
        for (int el = 0; el < 2; ++el) {
            const float2* xp = (const float2*)(x + ((size_t)t * BATCH + eglob + el) * 10);
            float2 xv[5];
#pragma unroll
            for (int i = 0; i < 5; ++i) xv[i] = xp[i];

            u64 acc[8];
#pragma unroll
            for (int p = 0; p < 8; ++p) acc[p] = 0ull;
#pragma unroll
            for (int i = 0; i < 10; ++i) {
                const ulonglong2* wp = (const ulonglong2*)(w1 + i * 8);
                ulonglong2 wa = wp[0], wb = wp[1], wc = wp[2], wd = wp[3];
                float xf = (i & 1) ? xv[i >> 1].y : xv[i >> 1].x;
                u64 xd = pack2(xf, xf);
                acc[0] = ffma2(xd, wa.x, acc[0]);
                acc[1] = ffma2(xd, wa.y, acc[1]);
                acc[2] = ffma2(xd, wb.x, acc[2]);
                acc[3] = ffma2(xd, wb.y, acc[3]);
                acc[4] = ffma2(xd, wc.x, acc[4]);
                acc[5] = ffma2(xd, wc.y, acc[5]);
                acc[6] = ffma2(xd, wd.x, acc[6]);
                acc[7] = ffma2(xd, wd.y, acc[7]);
            }
            u32 m16 = 0;
#pragma unroll
            for (int p = 0; p < 8; ++p)
                m16 |= lif_pair(acc[p], m1[el][2 * p], m1[el][2 * p + 1]) << (2 * p);
            // pre-shift into its 16-bit slot of the lo/hi word
            my1[el * 32] = (wq & 1) ? (m16 << 16) : m16;
        }
        __syncthreads();
        u32 lo[2], hi[2];
#pragma unroll
        for (int el = 0; el < 2; ++el) {
            u32 s0 = sp1[0 * 64 + el * 32 + lane];
            u32 s1 = sp1[1 * 64 + el * 32 + lane];
            u32 s2 = sp1[2 * 64 + el * 32 + lane];
            u32 s3 = sp1[3 * 64 + el * 32 + lane];
            lo[el] = s0 | s1;     // L1 outputs 0..31
            hi[el] = s2 | s3;     // L1 outputs 32..63
        }

        // ================= Layer 2: 64 -> 32 (4 pairs per warp) =================
        u64 acc2[2][4];
#pragma unroll
        for (int el = 0; el < 2; ++el)
#pragma unroll
            for (int p = 0; p < 4; ++p) acc2[el][p] = 0ull;
#pragma unroll
        for (int i = 0; i < 64; ++i) {
            const ulonglong2* wp = (const ulonglong2*)(w2 + i * 4);
            ulonglong2 wa = wp[0], wb = wp[1];
            u32 bit = 1u << (i & 31);
            u64 h0 = (((i < 32) ? lo[0] : hi[0]) & bit) ? ONE2 : 0ull;
            u64 h1 = (((i < 32) ? lo[1] : hi[1]) & bit) ? ONE2 : 0ull;
            acc2[0][0] = ffma2(h0, wa.x, acc2[0][0]);
            acc2[0][1] = ffma2(h0, wa.y, acc2[0][1]);
            acc2[0][2] = ffma2(h0, wb.x, acc2[0][2]);
            acc2[0][3] = ffma2(h0, wb.y, acc2[0][3]);
            acc2[1][0] = ffma2(h1, wa.x, acc2[1][0]);
            acc2[1][1] = ffma2(h1, wa.y, acc2[1][1]);
            acc2[1][2] = ffma2(h1, wb.x, acc2[1][2]);
            acc2[1][3] = ffma2(h1, wb.y, acc2[1][3]);
        }
#pragma unroll
        for (int el = 0; el < 2; ++el) {
            u32 m8 = 0;
#pragma unroll
            for (int p = 0; p < 4; ++p)
                m8 |= lif_pair(acc2[el][p], m2[el][2 * p], m2[el][2 * p + 1]) << (2 * p);
            my2[el * 32] = m8 << (wq * 8);
        }
        __syncthreads();
        u32 f2[2];
#pragma unroll
        for (int el = 0; el < 2; ++el) {
            u32 s0 = sp2[0 * 64 + el * 32 + lane];
            u32 s1 = sp2[1 * 64 + el * 32 + lane];
            u32 s2 = sp2[2 * 64 + el * 32 + lane];
            u32 s3 = sp2[3 * 64 + el * 32 + lane];
            f2[el] = (s0 | s1) | (s2 | s3);
        }

        // ================= Layer 3: 32 -> 32 =================
        u64 acc3[2][4];
#pragma unroll
        for (int el = 0; el < 2; ++el)
#pragma unroll
            for (int p = 0; p < 4; ++p) acc3[el][p] = 0ull;
#pragma unroll
        for (int i = 0; i < 32; ++i) {
            const ulonglong2* wp = (const ulonglong2*)(w3 + i * 4);
            ulonglong2 wa = wp[0], wb = wp[1];
            u32 bit = 1u << i;
            u64 h0 = (f2[0] & bit) ? ONE2 : 0ull;
            u64 h1 = (f2[1] & bit) ? ONE2 : 0ull;
            acc3[0][0] = ffma2(h0, wa.x, acc3[0][0]);
            acc3[0][1] = ffma2(h0, wa.y, acc3[0][1]);
            acc3[0][2] = ffma2(h0, wb.x, acc3[0][2]);
            acc3[0][3] = ffma2(h0, wb.y, acc3[0][3]);
            acc3[1][0] = ffma2(h1, wa.x, acc3[1][0]);
            acc3[1][1] = ffma2(h1, wa.y, acc3[1][1]);
            acc3[1][2] = ffma2(h1, wb.x, acc3[1][2]);
            acc3[1][3] = ffma2(h1, wb.y, acc3[1][3]);
        }
#pragma unroll
        for (int el = 0; el < 2; ++el) {
            u32 m8 = 0;
#pragma unroll
            for (int p = 0; p < 4; ++p)
                m8 |= lif_pair(acc3[el][p], m3[el][2 * p], m3[el][2 * p + 1]) << (2 * p);
            my3[el * 32] = m8 << (wq * 8);
        }
        __syncthreads();
        u32 f3[2];
#pragma unroll
        for (int el = 0; el < 2; ++el) {
            u32 s0 = sp3[0 * 64 + el * 32 + lane];
            u32 s1 = sp3[1 * 64 + el * 32 + lane];
            u32 s2 = sp3[2 * 64 + el * 32 + lane];
            u32 s3 = sp3[3 * 64 + el * 32 + lane];
            f3[el] = (s0 | s1) | (s2 | s3);
        }

        // ================= Layer 4: 32 -> 16 (2 pairs per warp) =================
        u64 acc4[2][2];
#pragma unroll
        for (int el = 0; el < 2; ++el) { acc4[el][0] = 0ull; acc4[el][1] = 0ull; }
#pragma unroll
        for (int i = 0; i < 32; ++i) {
            const ulonglong2* wp = (const ulonglong2*)(w4 + i * 2);
            ulonglong2 wa = wp[0];
            u32 bit = 1u << i;
            u64 h0 = (f3[0] & bit) ? ONE2 : 0ull;
            u64 h1 = (f3[1] & bit) ? ONE2 : 0ull;
            acc4[0][0] = ffma2(h0, wa.x, acc4[0][0]);
            acc4[0][1] = ffma2(h0, wa.y, acc4[0][1]);
            acc4[1][0] = ffma2(h1, wa.x, acc4[1][0]);
            acc4[1][1] = ffma2(h1, wa.y, acc4[1][1]);
        }
#pragma unroll
        for (int el = 0; el < 2; ++el) {
            u32 m4b = lif_pair(acc4[el][0], m4[el][0], m4[el][1])
                    | (lif_pair(acc4[el][1], m4[el][2], m4[el][3]) << 2);
            my4[el * 32] = m4b << (wq * 4);
        }
        __syncthreads();
        u32 f4[2];
#pragma unroll
        for (int el = 0; el < 2; ++el) {
            u32 s0 = sp4[0 * 64 + el * 32 + lane];
            u32 s1 = sp4[1 * 64 + el * 32 + lane];
            u32 s2 = sp4[2 * 64 + el * 32 + lane];
            u32 s3 = sp4[3 * 64 + el * 32 + lane];
            f4[el] = (s0 | s1) | (s2 | s3);
        }

        // ================= Layer 5: 16 -> 6 (padded; 1 pair per warp) ============
        u64 acc5[2];
        acc5[0] = 0ull; acc5[1] = 0ull;
#pragma unroll
        for (int i = 0; i < 16; ++i) {
            u64 w = w5[i];
            u32 bit = 1u << i;
            u64 h0 = (f4[0] & bit) ? ONE2 : 0ull;
            u64 h1 = (f4[1] & bit) ? ONE2 : 0ull;
            acc5[0] = ffma2(h0, w, acc5[0]);
            acc5[1] = ffma2(h1, w, acc5[1]);
        }
#pragma unroll
        for (int el = 0; el < 2; ++el) {
            float a0, a1; unpack2(acc5[el], a0, a1);
            float r0 = m5[el][0] > THRESHF ? THRESHF : 0.0f;
            float r1 = m5[el][1] > THRESHF ? THRESHF : 0.0f;
            float mm0 = fmaf(BETAF, m5[el][0], a0 - r0);
            float mm1 = fmaf(BETAF, m5[el][1], a1 - r1);
            m5[el][0] = mm0; m5[el][1] = mm1;
            if (wq < 3) {
                float2 o;
                o.x = mm0 > THRESHF ? 1.0f : 0.0f;
                o.y = mm1 > THRESHF ? 1.0f : 0.0f;
                *(float2*)(out + ((size_t)t * BATCH + eglob + el) * 6 + wq * 2) = o;
            }
        }
    }
}

extern "C" void kernel_launch(void* const* d_in, const int* in_sizes, int n_in,
                              void* d_out, int out_size) {
    const float *x = nullptr, *W1 = nullptr, *W2 = nullptr, *W3 = nullptr,
                *W4 = nullptr, *W5 = nullptr;
    for (int i = 0; i < n_in; ++i) {
        const float* p = (const float*)d_in[i];
        switch (in_sizes[i]) {
            case 52428800: x  = p; break;  // (20, 262144, 10)
            case 640:      W1 = p; break;  // (64, 10)
            case 2048:     W2 = p; break;  // (32, 64)
            case 1024:     W3 = p; break;  // (32, 32)
            case 512:      W4 = p; break;  // (16, 32)
            case 96:       W5 = p; break;  // (6, 16)
            default: break;
        }
    }
    float* out = (float*)d_out;
    // 4 warps per block = 4 output-quarters; 32 lanes x E=2 -> 64 elements per block
    lif_kernel<<<BATCH / 64, 128>>>(x, W1, W2, W3, W4, W5, out);
}